// round 10
// baseline (speedup 1.0000x reference)
#include <cuda_runtime.h>
#include <cstdint>

#define N_RAYS    8192
#define N_SAMPLES 256
#define HIDDEN    64
#define WPB       8              // warps (rays) per block
#define SPL       8              // samples per lane (256 / 32)
#define NPAIR     4              // packed f32x2 pairs per lane
#define OUT_STRIDE 261           // 3 color + depth + missed + 256 probs

typedef unsigned long long u64;

union F2 { u64 v; float2 f; uint2 u; };

__device__ __forceinline__ u64 pack2(float lo, float hi) {
    u64 r; asm("mov.b64 %0, {%1, %2};" : "=l"(r) : "f"(lo), "f"(hi)); return r;
}
__device__ __forceinline__ u64 fma2(u64 a, u64 b, u64 c) {
    u64 d; asm("fma.rn.f32x2 %0, %1, %2, %3;" : "=l"(d) : "l"(a), "l"(b), "l"(c)); return d;
}
__device__ __forceinline__ u64 add2(u64 a, u64 b) {
    u64 d; asm("add.rn.f32x2 %0, %1, %2;" : "=l"(d) : "l"(a), "l"(b)); return d;
}

__device__ __forceinline__ float sigmoidf_fast(float x) {
    return 1.0f / (1.0f + __expf(-x));
}

__global__ __launch_bounds__(WPB * 32, 4)
void volume_render_kernel(
    const float* __restrict__ ray_start,   // [N,3]
    const float* __restrict__ ray_dir,     // [N,3]
    const float* __restrict__ depth,       // [N,P]
    const float* __restrict__ dists,       // [N,P]
    const int*   __restrict__ sidx,        // [N,P] int32
    const float* __restrict__ W1,          // [3,64]
    const float* __restrict__ b1,          // [64]
    const float* __restrict__ wsig,        // [64]
    const float* __restrict__ Wrgb,        // [64,3]
    const float* __restrict__ Wdir,        // [3,3]
    const float* __restrict__ brgb,        // [3]
    float* __restrict__ out)               // [N,261]
{
    // Broadcast-packed weights, pre-halved for the (h+|h|)*(w/2) relu trick.
    __shared__ alignas(16) ulonglong2 wpA[HIDDEN];          // {wsig/2, wr/2} as {x,x},{y,y}
    __shared__ alignas(16) ulonglong2 wpB[HIDDEN];          // {wg/2,  wb/2}
    __shared__ alignas(16) ulonglong2 sdp[WPB][HIDDEN];     // {s,s},{d,d} per ray per channel

    const int tid  = threadIdx.x;
    const int lane = tid & 31;
    const int w    = tid >> 5;
    const int ray  = blockIdx.x * WPB + w;

    if (tid < HIDDEN) {
        float ws = 0.5f * wsig[tid];
        float wr = 0.5f * Wrgb[tid*3+0];
        float wg = 0.5f * Wrgb[tid*3+1];
        float wb = 0.5f * Wrgb[tid*3+2];
        wpA[tid] = make_ulonglong2(pack2(ws, ws), pack2(wr, wr));
        wpB[tid] = make_ulonglong2(pack2(wg, wg), pack2(wb, wb));
    }

    // Per-ray scalars (broadcast loads)
    const float sx = ray_start[ray*3+0], sy = ray_start[ray*3+1], sz = ray_start[ray*3+2];
    const float dx = ray_dir[ray*3+0],   dy = ray_dir[ray*3+1],   dz = ray_dir[ray*3+2];

    // Per-ray channel decomposition: h_j(t) = relu(s_j + t * d_j)
    #pragma unroll
    for (int j = lane; j < HIDDEN; j += 32) {
        float s = fmaf(sx, W1[j], fmaf(sy, W1[HIDDEN + j], fmaf(sz, W1[2*HIDDEN + j], b1[j])));
        float d = fmaf(dx, W1[j], fmaf(dy, W1[HIDDEN + j], dz * W1[2*HIDDEN + j]));
        sdp[w][j] = make_ulonglong2(pack2(s, s), pack2(d, d));
    }
    __syncthreads();

    // Each lane owns SPL contiguous samples: [lane*8, lane*8+8)
    const int sbase = ray * N_SAMPLES + lane * SPL;

    // Depths, kept only in packed form during the hot loop (saves 8 regs)
    u64 t2[NPAIR];
    {
        const float4* dp = reinterpret_cast<const float4*>(depth + sbase);
        float4 a = dp[0], b = dp[1];
        t2[0]=pack2(a.x,a.y); t2[1]=pack2(a.z,a.w);
        t2[2]=pack2(b.x,b.y); t2[3]=pack2(b.z,b.w);
    }

    // Packed accumulators
    u64 sig2[NPAIR], cr2[NPAIR], cg2[NPAIR], cb2[NPAIR];
    #pragma unroll
    for (int p = 0; p < NPAIR; p++) { sig2[p]=0ull; cr2[p]=0ull; cg2[p]=0ull; cb2[p]=0ull; }

    // Main MLP loop, packed f32x2: per pair
    //   h2   = s + t*d                       (1 fma2)
    //   hs2  = h2 + |h2| = 2*relu(h)         (2 LOP3 + 1 add2)
    //   acc += hs2 * (w/2)                   (4 fma2)
    #pragma unroll 8
    for (int j = 0; j < HIDDEN; j++) {
        const ulonglong2 sd = sdp[w][j];       // LDS.128 broadcast
        const ulonglong2 wA = wpA[j];          // LDS.128 broadcast
        const ulonglong2 wB = wpB[j];          // LDS.128 broadcast
        const u64 ss = sd.x, dd = sd.y;
        #pragma unroll
        for (int p = 0; p < NPAIR; p++) {
            u64 h  = fma2(dd, t2[p], ss);
            u64 ha = h & 0x7FFFFFFF7FFFFFFFULL;   // |.| per half (2x LOP3, alu pipe)
            u64 hs = add2(h, ha);                 // 2*relu(h), exact
            sig2[p] = fma2(hs, wA.x, sig2[p]);
            cr2[p]  = fma2(hs, wA.y, cr2[p]);
            cg2[p]  = fma2(hs, wB.x, cg2[p]);
            cb2[p]  = fma2(hs, wB.y, cb2[p]);
        }
    }

    // ---- Epilogue (loads deferred to here to keep hot-loop regs low) ----

    // dists * 7 * mask
    float m7[SPL];
    {
        const float4* dp = reinterpret_cast<const float4*>(dists + sbase);
        float4 a = dp[0], b = dp[1];
        float dv[SPL] = {a.x,a.y,a.z,a.w,b.x,b.y,b.z,b.w};
        const int4* ip = reinterpret_cast<const int4*>(sidx + sbase);
        int4 i0 = ip[0], i1 = ip[1];
        int iv[SPL] = {i0.x, i0.y, i0.z, i0.w, i1.x, i1.y, i1.z, i1.w};
        #pragma unroll
        for (int k = 0; k < SPL; k++) {
            m7[k] = (iv[k] != -1) ? 7.0f * dv[k] : 0.0f;
        }
    }

    // Unpack accumulators + depths (register aliasing; no math)
    float sig[SPL], cr[SPL], cg[SPL], cb[SPL], t[SPL];
    #pragma unroll
    for (int p = 0; p < NPAIR; p++) {
        F2 a; a.v = sig2[p]; sig[2*p]=a.f.x; sig[2*p+1]=a.f.y;
        F2 b; b.v = cr2[p];  cr[2*p]=b.f.x;  cr[2*p+1]=b.f.y;
        F2 c; c.v = cg2[p];  cg[2*p]=c.f.x;  cg[2*p+1]=c.f.y;
        F2 d; d.v = cb2[p];  cb[2*p]=d.f.x;  cb[2*p+1]=d.f.y;
        F2 e; e.v = t2[p];   t[2*p]=e.f.x;   t[2*p+1]=e.f.y;
    }

    // Direction color term: dir @ Wdir + brgb (cheap; recompute here, not held in loop)
    const float dir0 = fmaf(dx, Wdir[0], fmaf(dy, Wdir[3], fmaf(dz, Wdir[6], brgb[0])));
    const float dir1 = fmaf(dx, Wdir[1], fmaf(dy, Wdir[4], fmaf(dz, Wdir[7], brgb[1])));
    const float dir2 = fmaf(dx, Wdir[2], fmaf(dy, Wdir[5], fmaf(dz, Wdir[8], brgb[2])));

    // free energy + local exclusive prefix
    float fe[SPL], excl[SPL];
    float run = 0.0f;
    #pragma unroll
    for (int k = 0; k < SPL; k++) {
        fe[k] = fmaxf(sig[k], 0.0f) * m7[k];
        excl[k] = run;
        run += fe[k];
    }

    // Warp exclusive scan of lane totals
    float incl = run;
    #pragma unroll
    for (int off = 1; off < 32; off <<= 1) {
        float n = __shfl_up_sync(0xffffffffu, incl, off);
        if (lane >= off) incl += n;
    }
    const float offset = incl - run;   // exclusive prefix of this lane's block

    // probs: prob_k = (1 - exp(-fe_k)) * exp(-(offset + excl_k))
    float prob[SPL];
    #pragma unroll
    for (int k = 0; k < SPL; k++) {
        float a = -expm1f(-fe[k]);
        float b = expf(-(offset + excl[k]));
        prob[k] = a * b;
    }

    // Per-lane weighted accumulation + prob stores
    float dsum = 0.f, psum = 0.f, ar = 0.f, ag = 0.f, ab = 0.f;
    float* orow = out + (size_t)ray * OUT_STRIDE;
    #pragma unroll
    for (int k = 0; k < SPL; k++) {
        const float p = prob[k];
        dsum = fmaf(t[k], p, dsum);
        psum += p;
        ar = fmaf(sigmoidf_fast(cr[k] + dir0), p, ar);
        ag = fmaf(sigmoidf_fast(cg[k] + dir1), p, ag);
        ab = fmaf(sigmoidf_fast(cb[k] + dir2), p, ab);
        orow[5 + lane * SPL + k] = p;
    }

    // Warp reduction of the 5 scalars
    #pragma unroll
    for (int off = 16; off > 0; off >>= 1) {
        dsum += __shfl_xor_sync(0xffffffffu, dsum, off);
        psum += __shfl_xor_sync(0xffffffffu, psum, off);
        ar   += __shfl_xor_sync(0xffffffffu, ar,   off);
        ag   += __shfl_xor_sync(0xffffffffu, ag,   off);
        ab   += __shfl_xor_sync(0xffffffffu, ab,   off);
    }
    if (lane == 0) {
        orow[0] = ar;
        orow[1] = ag;
        orow[2] = ab;
        orow[3] = dsum;
        orow[4] = 1.0f - psum;
    }
}

extern "C" void kernel_launch(void* const* d_in, const int* in_sizes, int n_in,
                              void* d_out, int out_size) {
    const float* ray_start = (const float*)d_in[0];
    const float* ray_dir   = (const float*)d_in[1];
    const float* depth     = (const float*)d_in[2];
    const float* dists     = (const float*)d_in[3];
    const int*   sidx      = (const int*)d_in[4];
    const float* W1        = (const float*)d_in[5];
    const float* b1        = (const float*)d_in[6];
    const float* wsig      = (const float*)d_in[7];
    const float* Wrgb      = (const float*)d_in[8];
    const float* Wdir      = (const float*)d_in[9];
    const float* brgb      = (const float*)d_in[10];
    float* out = (float*)d_out;

    dim3 grid(N_RAYS / WPB);   // 1024 blocks
    dim3 block(WPB * 32);      // 256 threads = 8 warps = 8 rays
    volume_render_kernel<<<grid, block>>>(ray_start, ray_dir, depth, dists, sidx,
                                          W1, b1, wsig, Wrgb, Wdir, brgb, out);
}

// round 12
// speedup vs baseline: 1.2209x; 1.2209x over previous
#include <cuda_runtime.h>
#include <cstdint>

#define N_RAYS    8192
#define N_SAMPLES 256
#define HIDDEN    64
#define WPB       8              // warps (rays) per block
#define SPL       8              // samples per lane (256 / 32)
#define OUT_STRIDE 261           // 3 color + depth + missed + 256 probs

typedef unsigned long long u64;

union F2 { u64 v; float2 f; uint2 u; };

__device__ __forceinline__ u64 pack2(float lo, float hi) {
    u64 r; asm("mov.b64 %0, {%1, %2};" : "=l"(r) : "f"(lo), "f"(hi)); return r;
}
__device__ __forceinline__ u64 fma2(u64 a, u64 b, u64 c) {
    u64 d; asm("fma.rn.f32x2 %0, %1, %2, %3;" : "=l"(d) : "l"(a), "l"(b), "l"(c)); return d;
}

__device__ __forceinline__ float sigmoidf_fast(float x) {
    return 1.0f / (1.0f + __expf(-x));
}

__global__ __launch_bounds__(WPB * 32)
void volume_render_kernel(
    const float* __restrict__ ray_start,   // [N,3]
    const float* __restrict__ ray_dir,     // [N,3]
    const float* __restrict__ depth,       // [N,P]
    const float* __restrict__ dists,       // [N,P]
    const int*   __restrict__ sidx,        // [N,P] int32
    const float* __restrict__ W1,          // [3,64]
    const float* __restrict__ b1,          // [64]
    const float* __restrict__ wsig,        // [64]
    const float* __restrict__ Wrgb,        // [64,3]
    const float* __restrict__ Wdir,        // [3,3]
    const float* __restrict__ brgb,        // [3]
    float* __restrict__ out)               // [N,261]
{
    // Output-packed weights: per channel {wr,wg} and {wsig,wb}
    __shared__ alignas(16) ulonglong2 wRGSB[HIDDEN];        // {.x = {wr,wg}, .y = {wsig,wb}}
    __shared__ float2 sdw[WPB][HIDDEN];                     // {s_j, d_j} per ray per channel

    const int tid  = threadIdx.x;
    const int lane = tid & 31;
    const int w    = tid >> 5;
    const int ray  = blockIdx.x * WPB + w;

    if (tid < HIDDEN) {
        float wr = Wrgb[tid*3+0];
        float wg = Wrgb[tid*3+1];
        float wb = Wrgb[tid*3+2];
        float ws = wsig[tid];
        wRGSB[tid] = make_ulonglong2(pack2(wr, wg), pack2(ws, wb));
    }

    // Per-ray scalars (broadcast loads)
    const float sx = ray_start[ray*3+0], sy = ray_start[ray*3+1], sz = ray_start[ray*3+2];
    const float dx = ray_dir[ray*3+0],   dy = ray_dir[ray*3+1],   dz = ray_dir[ray*3+2];

    // Direction color term: dir @ Wdir + brgb
    const float dir0 = fmaf(dx, Wdir[0], fmaf(dy, Wdir[3], fmaf(dz, Wdir[6], brgb[0])));
    const float dir1 = fmaf(dx, Wdir[1], fmaf(dy, Wdir[4], fmaf(dz, Wdir[7], brgb[1])));
    const float dir2 = fmaf(dx, Wdir[2], fmaf(dy, Wdir[5], fmaf(dz, Wdir[8], brgb[2])));

    // Per-ray channel decomposition: h_j(t) = relu(s_j + t * d_j)
    #pragma unroll
    for (int j = lane; j < HIDDEN; j += 32) {
        float s = fmaf(sx, W1[j], fmaf(sy, W1[HIDDEN + j], fmaf(sz, W1[2*HIDDEN + j], b1[j])));
        float d = fmaf(dx, W1[j], fmaf(dy, W1[HIDDEN + j], dz * W1[2*HIDDEN + j]));
        sdw[w][j] = make_float2(s, d);
    }
    __syncthreads();

    // Each lane owns SPL contiguous samples: [lane*8, lane*8+8)
    const int sbase = ray * N_SAMPLES + lane * SPL;

    float t[SPL];
    {
        const float4* dp = reinterpret_cast<const float4*>(depth + sbase);
        float4 a = dp[0], b = dp[1];
        t[0]=a.x; t[1]=a.y; t[2]=a.z; t[3]=a.w;
        t[4]=b.x; t[5]=b.y; t[6]=b.z; t[7]=b.w;
    }
    float m7[SPL];   // dists * 7 * mask
    {
        const float4* dp = reinterpret_cast<const float4*>(dists + sbase);
        float4 a = dp[0], b = dp[1];
        float dv[SPL] = {a.x,a.y,a.z,a.w,b.x,b.y,b.z,b.w};
        const int4* ip = reinterpret_cast<const int4*>(sidx + sbase);
        int4 i0 = ip[0], i1 = ip[1];
        int iv[SPL] = {i0.x, i0.y, i0.z, i0.w, i1.x, i1.y, i1.z, i1.w};
        #pragma unroll
        for (int k = 0; k < SPL; k++) {
            m7[k] = (iv[k] != -1) ? 7.0f * dv[k] : 0.0f;
        }
    }

    // Output-packed accumulators: rg[s] = {r_s, g_s}, sb[s] = {sig_s, b_s}
    u64 rg[SPL], sb[SPL];
    #pragma unroll
    for (int k = 0; k < SPL; k++) { rg[k]=0ull; sb[k]=0ull; }

    // Main MLP loop: per channel per sample
    //   h   = s + t*d        scalar FFMA  (fma pipe, rt 2)
    //   hs  = max(h, 0)      FMNMX        (alu pipe)
    //   hh  = {hs, hs}       reg-pair dup (1 MOV)
    //   rg += hh * {wr,wg}   fma2
    //   sb += hh * {ws,wb}   fma2
    #pragma unroll 4
    for (int j = 0; j < HIDDEN; j++) {
        const float2 sd = sdw[w][j];           // LDS.64 broadcast
        const ulonglong2 wj = wRGSB[j];        // LDS.128 broadcast
        #pragma unroll
        for (int k = 0; k < SPL; k++) {
            float h  = fmaf(sd.y, t[k], sd.x);
            float hs = fmaxf(h, 0.0f);
            u64 hh   = pack2(hs, hs);
            rg[k] = fma2(hh, wj.x, rg[k]);
            sb[k] = fma2(hh, wj.y, sb[k]);
        }
    }

    // Unpack accumulators (register aliasing; no math)
    float sig[SPL], cr[SPL], cg[SPL], cb[SPL];
    #pragma unroll
    for (int k = 0; k < SPL; k++) {
        F2 a; a.v = rg[k]; cr[k]=a.f.x; cg[k]=a.f.y;
        F2 b; b.v = sb[k]; sig[k]=b.f.x; cb[k]=b.f.y;
    }

    // free energy + local exclusive prefix
    float fe[SPL], excl[SPL];
    float run = 0.0f;
    #pragma unroll
    for (int k = 0; k < SPL; k++) {
        fe[k] = fmaxf(sig[k], 0.0f) * m7[k];
        excl[k] = run;
        run += fe[k];
    }

    // Warp exclusive scan of lane totals
    float incl = run;
    #pragma unroll
    for (int off = 1; off < 32; off <<= 1) {
        float n = __shfl_up_sync(0xffffffffu, incl, off);
        if (lane >= off) incl += n;
    }
    const float offset = incl - run;   // exclusive prefix of this lane's block

    // probs: prob_k = (1 - exp(-fe_k)) * exp(-(offset + excl_k))
    float prob[SPL];
    #pragma unroll
    for (int k = 0; k < SPL; k++) {
        float a = -expm1f(-fe[k]);
        float b = expf(-(offset + excl[k]));
        prob[k] = a * b;
    }

    // Per-lane weighted accumulation + prob stores
    float dsum = 0.f, psum = 0.f, ar = 0.f, ag = 0.f, ab = 0.f;
    float* orow = out + (size_t)ray * OUT_STRIDE;
    #pragma unroll
    for (int k = 0; k < SPL; k++) {
        const float p = prob[k];
        dsum = fmaf(t[k], p, dsum);
        psum += p;
        ar = fmaf(sigmoidf_fast(cr[k] + dir0), p, ar);
        ag = fmaf(sigmoidf_fast(cg[k] + dir1), p, ag);
        ab = fmaf(sigmoidf_fast(cb[k] + dir2), p, ab);
        orow[5 + lane * SPL + k] = p;
    }

    // Warp reduction of the 5 scalars
    #pragma unroll
    for (int off = 16; off > 0; off >>= 1) {
        dsum += __shfl_xor_sync(0xffffffffu, dsum, off);
        psum += __shfl_xor_sync(0xffffffffu, psum, off);
        ar   += __shfl_xor_sync(0xffffffffu, ar,   off);
        ag   += __shfl_xor_sync(0xffffffffu, ag,   off);
        ab   += __shfl_xor_sync(0xffffffffu, ab,   off);
    }
    if (lane == 0) {
        orow[0] = ar;
        orow[1] = ag;
        orow[2] = ab;
        orow[3] = dsum;
        orow[4] = 1.0f - psum;
    }
}

extern "C" void kernel_launch(void* const* d_in, const int* in_sizes, int n_in,
                              void* d_out, int out_size) {
    const float* ray_start = (const float*)d_in[0];
    const float* ray_dir   = (const float*)d_in[1];
    const float* depth     = (const float*)d_in[2];
    const float* dists     = (const float*)d_in[3];
    const int*   sidx      = (const int*)d_in[4];
    const float* W1        = (const float*)d_in[5];
    const float* b1        = (const float*)d_in[6];
    const float* wsig      = (const float*)d_in[7];
    const float* Wrgb      = (const float*)d_in[8];
    const float* Wdir      = (const float*)d_in[9];
    const float* brgb      = (const float*)d_in[10];
    float* out = (float*)d_out;

    dim3 grid(N_RAYS / WPB);   // 1024 blocks
    dim3 block(WPB * 32);      // 256 threads = 8 warps = 8 rays
    volume_render_kernel<<<grid, block>>>(ray_start, ray_dir, depth, dists, sidx,
                                          W1, b1, wsig, Wrgb, Wdir, brgb, out);
}

// round 15
// speedup vs baseline: 1.5096x; 1.2365x over previous
#include <cuda_runtime.h>
#include <cstdint>

#define N_RAYS    8192
#define N_SAMPLES 256
#define HIDDEN    64
#define WPB       4              // warps (rays) per block
#define SPL       8              // samples per lane (256 / 32)
#define NDIFF     264            // 257 needed, padded for float4 zeroing
#define OUT_STRIDE 261           // 3 color + depth + missed + 256 probs

__device__ __forceinline__ float sigmoidf_fast(float x) {
    return 1.0f / (1.0f + __expf(-x));
}

__global__ __launch_bounds__(WPB * 32)
void volume_render_kernel(
    const float* __restrict__ ray_start,   // [N,3]
    const float* __restrict__ ray_dir,     // [N,3]
    const float* __restrict__ depth,       // [N,P] sorted along P
    const float* __restrict__ dists,       // [N,P]
    const int*   __restrict__ sidx,        // [N,P] int32
    const float* __restrict__ W1,          // [3,64]
    const float* __restrict__ b1,          // [64]
    const float* __restrict__ wsig,        // [64]
    const float* __restrict__ Wrgb,        // [64,3]
    const float* __restrict__ Wdir,        // [3,3]
    const float* __restrict__ brgb,        // [3]
    float* __restrict__ out)               // [N,261]
{
    // Per-ray sorted depths (for breakpoint binary search) + difference arrays.
    // diffS[w][c][p]: c = 0..3 -> A(sig,r,g,b) deltas, c = 4..7 -> B deltas.
    __shared__ alignas(16) float tS[WPB][N_SAMPLES];
    __shared__ alignas(16) float diffS[WPB][8][NDIFF];

    const int tid  = threadIdx.x;
    const int lane = tid & 31;
    const int w    = tid >> 5;
    const int ray  = blockIdx.x * WPB + w;

    // Zero this warp's diff arrays
    {
        float4* dz = reinterpret_cast<float4*>(&diffS[w][0][0]);
        for (int i = lane; i < (8 * NDIFF) / 4; i += 32)
            dz[i] = make_float4(0.f, 0.f, 0.f, 0.f);
    }

    // Load this lane's 8 depths; mirror the full sorted array into smem
    const int sbase = ray * N_SAMPLES + lane * SPL;
    float t[SPL];
    {
        const float4* dp = reinterpret_cast<const float4*>(depth + sbase);
        float4 a = dp[0], b = dp[1];
        t[0]=a.x; t[1]=a.y; t[2]=a.z; t[3]=a.w;
        t[4]=b.x; t[5]=b.y; t[6]=b.z; t[7]=b.w;
        float4* ts = reinterpret_cast<float4*>(&tS[w][lane * SPL]);
        ts[0] = a; ts[1] = b;
    }

    // Per-ray scalars
    const float sx = ray_start[ray*3+0], sy = ray_start[ray*3+1], sz = ray_start[ray*3+2];
    const float dx = ray_dir[ray*3+0],   dy = ray_dir[ray*3+1],   dz = ray_dir[ray*3+2];

    const float dir0 = fmaf(dx, Wdir[0], fmaf(dy, Wdir[3], fmaf(dz, Wdir[6], brgb[0])));
    const float dir1 = fmaf(dx, Wdir[1], fmaf(dy, Wdir[4], fmaf(dz, Wdir[7], brgb[1])));
    const float dir2 = fmaf(dx, Wdir[2], fmaf(dy, Wdir[5], fmaf(dz, Wdir[8], brgb[2])));

    __syncwarp();   // tS + zeroed diffS visible to the warp

    const float tmin = tS[w][0];
    const float tmax = tS[w][N_SAMPLES - 1];

    // Event generation: channels j = lane, lane+32.
    // h_j(t) = s_j + t*d_j ; active set changes at key = -s/d.
    float baseA0=0.f, baseA1=0.f, baseA2=0.f, baseA3=0.f;
    float baseB0=0.f, baseB1=0.f, baseB2=0.f, baseB3=0.f;

    #pragma unroll
    for (int e = 0; e < 2; e++) {
        const int j = lane + e * 32;
        const float s = fmaf(sx, W1[j], fmaf(sy, W1[HIDDEN + j], fmaf(sz, W1[2*HIDDEN + j], b1[j])));
        const float d = fmaf(dx, W1[j], fmaf(dy, W1[HIDDEN + j], dz * W1[2*HIDDEN + j]));
        const float w0 = wsig[j], w1r = Wrgb[3*j], w2g = Wrgb[3*j+1], w3b = Wrgb[3*j+2];
        const float aS = s*w0, aR = s*w1r, aG = s*w2g, aB = s*w3b;
        const float bS = d*w0, bR = d*w1r, bG = d*w2g, bB = d*w3b;

        if (d != 0.0f) {
            const float key = __fdividef(-s, d);
            // Classify against the sample range to avoid edge atomics:
            //   d > 0: active for t >= key
            //   d < 0: active for t <  key (present initially, removed at key)
            bool always, never, needs_event;
            if (d > 0.0f) {
                always = (key <= tmin);
                never  = (key >  tmax);
            } else {
                always = (key >  tmax);
                never  = (key <= tmin);
            }
            needs_event = !always && !never;

            if (always || (d < 0.0f && needs_event)) {
                baseA0 += aS; baseA1 += aR; baseA2 += aG; baseA3 += aB;
                baseB0 += bS; baseB1 += bR; baseB2 += bG; baseB3 += bB;
            }
            if (needs_event) {
                // lower_bound: p = #(t < key), p in (0, 256)
                int p = 0;
                #pragma unroll
                for (int st = 256; st > 0; st >>= 1) {
                    int c = p + st;
                    if (c <= N_SAMPLES && tS[w][c - 1] < key) p = c;
                }
                const float sg = (d > 0.0f) ? 1.0f : -1.0f;
                atomicAdd(&diffS[w][0][p], sg * aS);
                atomicAdd(&diffS[w][1][p], sg * aR);
                atomicAdd(&diffS[w][2][p], sg * aG);
                atomicAdd(&diffS[w][3][p], sg * aB);
                atomicAdd(&diffS[w][4][p], sg * bS);
                atomicAdd(&diffS[w][5][p], sg * bR);
                atomicAdd(&diffS[w][6][p], sg * bG);
                atomicAdd(&diffS[w][7][p], sg * bB);
            }
        } else if (s > 0.0f) {
            // constant active channel: contributes only to A
            baseA0 += aS; baseA1 += aR; baseA2 += aG; baseA3 += aB;
        }
    }

    // Warp-reduce base terms (all lanes end with totals)
    #pragma unroll
    for (int off = 16; off > 0; off >>= 1) {
        baseA0 += __shfl_xor_sync(0xffffffffu, baseA0, off);
        baseA1 += __shfl_xor_sync(0xffffffffu, baseA1, off);
        baseA2 += __shfl_xor_sync(0xffffffffu, baseA2, off);
        baseA3 += __shfl_xor_sync(0xffffffffu, baseA3, off);
        baseB0 += __shfl_xor_sync(0xffffffffu, baseB0, off);
        baseB1 += __shfl_xor_sync(0xffffffffu, baseB1, off);
        baseB2 += __shfl_xor_sync(0xffffffffu, baseB2, off);
        baseB3 += __shfl_xor_sync(0xffffffffu, baseB3, off);
    }

    __syncwarp();   // all atomics visible before scans

    const float baseAv[4] = {baseA0, baseA1, baseA2, baseA3};
    const float baseBv[4] = {baseB0, baseB1, baseB2, baseB3};

    // Prefix-scan the diff arrays -> per-sample outputs out_c(s) = A_c(s) + t_s*B_c(s)
    float outv[4][SPL];
    #pragma unroll
    for (int c = 0; c < 4; c++) {
        // A channel
        float vA[SPL];
        {
            const float4* pa = reinterpret_cast<const float4*>(&diffS[w][c][lane * SPL]);
            float4 a0 = pa[0], a1 = pa[1];
            vA[0]=a0.x; vA[1]=a0.y; vA[2]=a0.z; vA[3]=a0.w;
            vA[4]=a1.x; vA[5]=a1.y; vA[6]=a1.z; vA[7]=a1.w;
        }
        #pragma unroll
        for (int k = 1; k < SPL; k++) vA[k] += vA[k-1];
        float runA = vA[7];
        float inclA = runA;
        #pragma unroll
        for (int off = 1; off < 32; off <<= 1) {
            float n = __shfl_up_sync(0xffffffffu, inclA, off);
            if (lane >= off) inclA += n;
        }
        const float offA = inclA - runA + baseAv[c];

        // B channel
        float vB[SPL];
        {
            const float4* pb = reinterpret_cast<const float4*>(&diffS[w][4 + c][lane * SPL]);
            float4 b0 = pb[0], b1v = pb[1];
            vB[0]=b0.x; vB[1]=b0.y; vB[2]=b0.z; vB[3]=b0.w;
            vB[4]=b1v.x; vB[5]=b1v.y; vB[6]=b1v.z; vB[7]=b1v.w;
        }
        #pragma unroll
        for (int k = 1; k < SPL; k++) vB[k] += vB[k-1];
        float runB = vB[7];
        float inclB = runB;
        #pragma unroll
        for (int off = 1; off < 32; off <<= 1) {
            float n = __shfl_up_sync(0xffffffffu, inclB, off);
            if (lane >= off) inclB += n;
        }
        const float offB = inclB - runB + baseBv[c];

        #pragma unroll
        for (int k = 0; k < SPL; k++)
            outv[c][k] = (offA + vA[k]) + t[k] * (offB + vB[k]);
    }

    // dists * 7 * mask
    float m7[SPL];
    {
        const float4* dp = reinterpret_cast<const float4*>(dists + sbase);
        float4 a = dp[0], b = dp[1];
        float dv[SPL] = {a.x,a.y,a.z,a.w,b.x,b.y,b.z,b.w};
        const int4* ip = reinterpret_cast<const int4*>(sidx + sbase);
        int4 i0 = ip[0], i1 = ip[1];
        int iv[SPL] = {i0.x, i0.y, i0.z, i0.w, i1.x, i1.y, i1.z, i1.w};
        #pragma unroll
        for (int k = 0; k < SPL; k++) {
            m7[k] = (iv[k] != -1) ? 7.0f * dv[k] : 0.0f;
        }
    }

    // free energy + local exclusive prefix
    float fe[SPL], excl[SPL];
    float run = 0.0f;
    #pragma unroll
    for (int k = 0; k < SPL; k++) {
        fe[k] = fmaxf(outv[0][k], 0.0f) * m7[k];
        excl[k] = run;
        run += fe[k];
    }

    // Warp exclusive scan of lane totals
    float incl = run;
    #pragma unroll
    for (int off = 1; off < 32; off <<= 1) {
        float n = __shfl_up_sync(0xffffffffu, incl, off);
        if (lane >= off) incl += n;
    }
    const float offset = incl - run;

    // probs
    float prob[SPL];
    #pragma unroll
    for (int k = 0; k < SPL; k++) {
        float a = -expm1f(-fe[k]);
        float b = expf(-(offset + excl[k]));
        prob[k] = a * b;
    }

    // Per-lane weighted accumulation + prob stores
    float dsum = 0.f, psum = 0.f, ar = 0.f, ag = 0.f, ab = 0.f;
    float* orow = out + (size_t)ray * OUT_STRIDE;
    #pragma unroll
    for (int k = 0; k < SPL; k++) {
        const float p = prob[k];
        dsum = fmaf(t[k], p, dsum);
        psum += p;
        ar = fmaf(sigmoidf_fast(outv[1][k] + dir0), p, ar);
        ag = fmaf(sigmoidf_fast(outv[2][k] + dir1), p, ag);
        ab = fmaf(sigmoidf_fast(outv[3][k] + dir2), p, ab);
        orow[5 + lane * SPL + k] = p;
    }

    // Warp reduction of the 5 scalars
    #pragma unroll
    for (int off = 16; off > 0; off >>= 1) {
        dsum += __shfl_xor_sync(0xffffffffu, dsum, off);
        psum += __shfl_xor_sync(0xffffffffu, psum, off);
        ar   += __shfl_xor_sync(0xffffffffu, ar,   off);
        ag   += __shfl_xor_sync(0xffffffffu, ag,   off);
        ab   += __shfl_xor_sync(0xffffffffu, ab,   off);
    }
    if (lane == 0) {
        orow[0] = ar;
        orow[1] = ag;
        orow[2] = ab;
        orow[3] = dsum;
        orow[4] = 1.0f - psum;
    }
}

extern "C" void kernel_launch(void* const* d_in, const int* in_sizes, int n_in,
                              void* d_out, int out_size) {
    const float* ray_start = (const float*)d_in[0];
    const float* ray_dir   = (const float*)d_in[1];
    const float* depth     = (const float*)d_in[2];
    const float* dists     = (const float*)d_in[3];
    const int*   sidx      = (const int*)d_in[4];
    const float* W1        = (const float*)d_in[5];
    const float* b1        = (const float*)d_in[6];
    const float* wsig      = (const float*)d_in[7];
    const float* Wrgb      = (const float*)d_in[8];
    const float* Wdir      = (const float*)d_in[9];
    const float* brgb      = (const float*)d_in[10];
    float* out = (float*)d_out;

    dim3 grid(N_RAYS / WPB);   // 2048 blocks
    dim3 block(WPB * 32);      // 128 threads = 4 warps = 4 rays
    volume_render_kernel<<<grid, block>>>(ray_start, ray_dir, depth, dists, sidx,
                                          W1, b1, wsig, Wrgb, Wdir, brgb, out);
}

// round 16
// speedup vs baseline: 1.5236x; 1.0092x over previous
#include <cuda_runtime.h>
#include <cstdint>

#define N_RAYS    8192
#define N_SAMPLES 256
#define HIDDEN    64
#define WPB       4              // warps (rays) per block
#define SPL       8              // samples per lane (256 / 32)
#define NDIFF     264            // 257 needed, padded for float4 zeroing
#define OUT_STRIDE 261           // 3 color + depth + missed + 256 probs

__device__ __forceinline__ float sigmoidf_fast(float x) {
    return 1.0f / (1.0f + __expf(-x));
}

// Scatter one event's 8 channel-deltas into the difference arrays.
// Collision-free lanes (unique p among active lanes) use plain STS / LDS+STS;
// only lanes whose p collides with another active lane fall back to atomics.
__device__ __forceinline__ void scatter_event(float* dbase, int p, const float* vals, bool first_round) {
    const unsigned act = __activemask();
    const unsigned mk  = __match_any_sync(act, p);
    if (__popc(mk) == 1) {
        if (first_round) {
            #pragma unroll
            for (int c = 0; c < 8; c++) dbase[c * NDIFF + p] = vals[c];      // slot is zero
        } else {
            #pragma unroll
            for (int c = 0; c < 8; c++) dbase[c * NDIFF + p] += vals[c];     // ordered by syncwarp
        }
    } else {
        #pragma unroll
        for (int c = 0; c < 8; c++) atomicAdd(&dbase[c * NDIFF + p], vals[c]);
    }
}

__global__ __launch_bounds__(WPB * 32)
void volume_render_kernel(
    const float* __restrict__ ray_start,   // [N,3]
    const float* __restrict__ ray_dir,     // [N,3]
    const float* __restrict__ depth,       // [N,P] sorted along P
    const float* __restrict__ dists,       // [N,P]
    const int*   __restrict__ sidx,        // [N,P] int32
    const float* __restrict__ W1,          // [3,64]
    const float* __restrict__ b1,          // [64]
    const float* __restrict__ wsig,        // [64]
    const float* __restrict__ Wrgb,        // [64,3]
    const float* __restrict__ Wdir,        // [3,3]
    const float* __restrict__ brgb,        // [3]
    float* __restrict__ out)               // [N,261]
{
    // Per-ray sorted depths (for breakpoint binary search) + difference arrays.
    // diffS[w][c][p]: c = 0..3 -> A(sig,r,g,b) deltas, c = 4..7 -> B deltas.
    __shared__ alignas(16) float tS[WPB][N_SAMPLES];
    __shared__ alignas(16) float diffS[WPB][8][NDIFF];

    const int tid  = threadIdx.x;
    const int lane = tid & 31;
    const int w    = tid >> 5;
    const int ray  = blockIdx.x * WPB + w;

    // Zero this warp's diff arrays
    {
        float4* dz = reinterpret_cast<float4*>(&diffS[w][0][0]);
        for (int i = lane; i < (8 * NDIFF) / 4; i += 32)
            dz[i] = make_float4(0.f, 0.f, 0.f, 0.f);
    }

    // Load this lane's 8 depths; mirror the full sorted array into smem
    const int sbase = ray * N_SAMPLES + lane * SPL;
    float t[SPL];
    {
        const float4* dp = reinterpret_cast<const float4*>(depth + sbase);
        float4 a = dp[0], b = dp[1];
        t[0]=a.x; t[1]=a.y; t[2]=a.z; t[3]=a.w;
        t[4]=b.x; t[5]=b.y; t[6]=b.z; t[7]=b.w;
        float4* ts = reinterpret_cast<float4*>(&tS[w][lane * SPL]);
        ts[0] = a; ts[1] = b;
    }

    // Per-ray scalars
    const float sx = ray_start[ray*3+0], sy = ray_start[ray*3+1], sz = ray_start[ray*3+2];
    const float dx = ray_dir[ray*3+0],   dy = ray_dir[ray*3+1],   dz = ray_dir[ray*3+2];

    const float dir0 = fmaf(dx, Wdir[0], fmaf(dy, Wdir[3], fmaf(dz, Wdir[6], brgb[0])));
    const float dir1 = fmaf(dx, Wdir[1], fmaf(dy, Wdir[4], fmaf(dz, Wdir[7], brgb[1])));
    const float dir2 = fmaf(dx, Wdir[2], fmaf(dy, Wdir[5], fmaf(dz, Wdir[8], brgb[2])));

    __syncwarp();   // tS + zeroed diffS visible to the warp

    const float tmin = tS[w][0];
    const float tmax = tS[w][N_SAMPLES - 1];

    // Event generation: channels j = lane, lane+32.
    // h_j(t) = s_j + t*d_j ; active set changes at key = -s/d.
    float baseA0=0.f, baseA1=0.f, baseA2=0.f, baseA3=0.f;
    float baseB0=0.f, baseB1=0.f, baseB2=0.f, baseB3=0.f;
    float* const dbase = &diffS[w][0][0];

    #pragma unroll
    for (int e = 0; e < 2; e++) {
        const int j = lane + e * 32;
        const float s = fmaf(sx, W1[j], fmaf(sy, W1[HIDDEN + j], fmaf(sz, W1[2*HIDDEN + j], b1[j])));
        const float d = fmaf(dx, W1[j], fmaf(dy, W1[HIDDEN + j], dz * W1[2*HIDDEN + j]));
        const float w0 = wsig[j], w1r = Wrgb[3*j], w2g = Wrgb[3*j+1], w3b = Wrgb[3*j+2];
        float vals[8];
        vals[0] = s*w0;  vals[1] = s*w1r; vals[2] = s*w2g; vals[3] = s*w3b;   // A deltas
        vals[4] = d*w0;  vals[5] = d*w1r; vals[6] = d*w2g; vals[7] = d*w3b;   // B deltas

        if (d != 0.0f) {
            const float key = __fdividef(-s, d);
            // Classify against the sample range to avoid edge scatters:
            //   d > 0: active for t >= key
            //   d < 0: active for t <  key (present initially, removed at key)
            bool always, never, needs_event;
            if (d > 0.0f) {
                always = (key <= tmin);
                never  = (key >  tmax);
            } else {
                always = (key >  tmax);
                never  = (key <= tmin);
            }
            needs_event = !always && !never;

            if (always || (d < 0.0f && needs_event)) {
                baseA0 += vals[0]; baseA1 += vals[1]; baseA2 += vals[2]; baseA3 += vals[3];
                baseB0 += vals[4]; baseB1 += vals[5]; baseB2 += vals[6]; baseB3 += vals[7];
            }
            if (needs_event) {
                // lower_bound: p = #(t < key), p in (0, 256)
                int p = 0;
                #pragma unroll
                for (int st = 256; st > 0; st >>= 1) {
                    int c = p + st;
                    if (c <= N_SAMPLES && tS[w][c - 1] < key) p = c;
                }
                if (d < 0.0f) {
                    #pragma unroll
                    for (int c = 0; c < 8; c++) vals[c] = -vals[c];
                }
                scatter_event(dbase, p, vals, e == 0);
            }
        } else if (s > 0.0f) {
            // constant active channel: contributes only to A
            baseA0 += vals[0]; baseA1 += vals[1]; baseA2 += vals[2]; baseA3 += vals[3];
        }
        __syncwarp();   // order round-0 scatters before round-1 read-modify-writes
    }

    // Warp-reduce base terms (all lanes end with totals)
    #pragma unroll
    for (int off = 16; off > 0; off >>= 1) {
        baseA0 += __shfl_xor_sync(0xffffffffu, baseA0, off);
        baseA1 += __shfl_xor_sync(0xffffffffu, baseA1, off);
        baseA2 += __shfl_xor_sync(0xffffffffu, baseA2, off);
        baseA3 += __shfl_xor_sync(0xffffffffu, baseA3, off);
        baseB0 += __shfl_xor_sync(0xffffffffu, baseB0, off);
        baseB1 += __shfl_xor_sync(0xffffffffu, baseB1, off);
        baseB2 += __shfl_xor_sync(0xffffffffu, baseB2, off);
        baseB3 += __shfl_xor_sync(0xffffffffu, baseB3, off);
    }

    __syncwarp();   // all scatters visible before scans

    const float baseAv[4] = {baseA0, baseA1, baseA2, baseA3};
    const float baseBv[4] = {baseB0, baseB1, baseB2, baseB3};

    // Prefix-scan the diff arrays -> per-sample outputs out_c(s) = A_c(s) + t_s*B_c(s)
    float outv[4][SPL];
    #pragma unroll
    for (int c = 0; c < 4; c++) {
        // A channel
        float vA[SPL];
        {
            const float4* pa = reinterpret_cast<const float4*>(&diffS[w][c][lane * SPL]);
            float4 a0 = pa[0], a1 = pa[1];
            vA[0]=a0.x; vA[1]=a0.y; vA[2]=a0.z; vA[3]=a0.w;
            vA[4]=a1.x; vA[5]=a1.y; vA[6]=a1.z; vA[7]=a1.w;
        }
        #pragma unroll
        for (int k = 1; k < SPL; k++) vA[k] += vA[k-1];
        float runA = vA[7];
        float inclA = runA;
        #pragma unroll
        for (int off = 1; off < 32; off <<= 1) {
            float n = __shfl_up_sync(0xffffffffu, inclA, off);
            if (lane >= off) inclA += n;
        }
        const float offA = inclA - runA + baseAv[c];

        // B channel
        float vB[SPL];
        {
            const float4* pb = reinterpret_cast<const float4*>(&diffS[w][4 + c][lane * SPL]);
            float4 b0 = pb[0], b1v = pb[1];
            vB[0]=b0.x; vB[1]=b0.y; vB[2]=b0.z; vB[3]=b0.w;
            vB[4]=b1v.x; vB[5]=b1v.y; vB[6]=b1v.z; vB[7]=b1v.w;
        }
        #pragma unroll
        for (int k = 1; k < SPL; k++) vB[k] += vB[k-1];
        float runB = vB[7];
        float inclB = runB;
        #pragma unroll
        for (int off = 1; off < 32; off <<= 1) {
            float n = __shfl_up_sync(0xffffffffu, inclB, off);
            if (lane >= off) inclB += n;
        }
        const float offB = inclB - runB + baseBv[c];

        #pragma unroll
        for (int k = 0; k < SPL; k++)
            outv[c][k] = (offA + vA[k]) + t[k] * (offB + vB[k]);
    }

    // dists * 7 * mask
    float m7[SPL];
    {
        const float4* dp = reinterpret_cast<const float4*>(dists + sbase);
        float4 a = dp[0], b = dp[1];
        float dv[SPL] = {a.x,a.y,a.z,a.w,b.x,b.y,b.z,b.w};
        const int4* ip = reinterpret_cast<const int4*>(sidx + sbase);
        int4 i0 = ip[0], i1 = ip[1];
        int iv[SPL] = {i0.x, i0.y, i0.z, i0.w, i1.x, i1.y, i1.z, i1.w};
        #pragma unroll
        for (int k = 0; k < SPL; k++) {
            m7[k] = (iv[k] != -1) ? 7.0f * dv[k] : 0.0f;
        }
    }

    // free energy + local exclusive prefix
    float fe[SPL], excl[SPL];
    float run = 0.0f;
    #pragma unroll
    for (int k = 0; k < SPL; k++) {
        fe[k] = fmaxf(outv[0][k], 0.0f) * m7[k];
        excl[k] = run;
        run += fe[k];
    }

    // Warp exclusive scan of lane totals
    float incl = run;
    #pragma unroll
    for (int off = 1; off < 32; off <<= 1) {
        float n = __shfl_up_sync(0xffffffffu, incl, off);
        if (lane >= off) incl += n;
    }
    const float offset = incl - run;

    // probs
    float prob[SPL];
    #pragma unroll
    for (int k = 0; k < SPL; k++) {
        float a = -expm1f(-fe[k]);
        float b = expf(-(offset + excl[k]));
        prob[k] = a * b;
    }

    // Per-lane weighted accumulation + prob stores
    float dsum = 0.f, psum = 0.f, ar = 0.f, ag = 0.f, ab = 0.f;
    float* orow = out + (size_t)ray * OUT_STRIDE;
    #pragma unroll
    for (int k = 0; k < SPL; k++) {
        const float p = prob[k];
        dsum = fmaf(t[k], p, dsum);
        psum += p;
        ar = fmaf(sigmoidf_fast(outv[1][k] + dir0), p, ar);
        ag = fmaf(sigmoidf_fast(outv[2][k] + dir1), p, ag);
        ab = fmaf(sigmoidf_fast(outv[3][k] + dir2), p, ab);
        orow[5 + lane * SPL + k] = p;
    }

    // Warp reduction of the 5 scalars
    #pragma unroll
    for (int off = 16; off > 0; off >>= 1) {
        dsum += __shfl_xor_sync(0xffffffffu, dsum, off);
        psum += __shfl_xor_sync(0xffffffffu, psum, off);
        ar   += __shfl_xor_sync(0xffffffffu, ar,   off);
        ag   += __shfl_xor_sync(0xffffffffu, ag,   off);
        ab   += __shfl_xor_sync(0xffffffffu, ab,   off);
    }
    if (lane == 0) {
        orow[0] = ar;
        orow[1] = ag;
        orow[2] = ab;
        orow[3] = dsum;
        orow[4] = 1.0f - psum;
    }
}

extern "C" void kernel_launch(void* const* d_in, const int* in_sizes, int n_in,
                              void* d_out, int out_size) {
    const float* ray_start = (const float*)d_in[0];
    const float* ray_dir   = (const float*)d_in[1];
    const float* depth     = (const float*)d_in[2];
    const float* dists     = (const float*)d_in[3];
    const int*   sidx      = (const int*)d_in[4];
    const float* W1        = (const float*)d_in[5];
    const float* b1        = (const float*)d_in[6];
    const float* wsig      = (const float*)d_in[7];
    const float* Wrgb      = (const float*)d_in[8];
    const float* Wdir      = (const float*)d_in[9];
    const float* brgb      = (const float*)d_in[10];
    float* out = (float*)d_out;

    dim3 grid(N_RAYS / WPB);   // 2048 blocks
    dim3 block(WPB * 32);      // 128 threads = 4 warps = 4 rays
    volume_render_kernel<<<grid, block>>>(ray_start, ray_dir, depth, dists, sidx,
                                          W1, b1, wsig, Wrgb, Wdir, brgb, out);
}